// round 2
// baseline (speedup 1.0000x reference)
#include <cuda_runtime.h>

#define N_NODES 100000
#define N_EDGES 1600000
#define IN_DIM  64
#define HID     128
#define OUT_DIM 16
#define NPB     32          // nodes per block in layer kernels
#define CHUNK   512
#define NCHUNK  ((N_NODES + CHUNK - 1) / CHUNK)   // 196

// ---------------- scratch (device globals; no allocation allowed) ----------
__device__ int   g_deg[N_NODES];
__device__ int   g_rowptr[N_NODES];
__device__ int   g_pos[N_NODES];
__device__ int   g_col[N_EDGES];
__device__ int   g_chunk[NCHUNK];
__device__ float g_h1[N_NODES * HID];     // relu(normalize(layer1 out))
__device__ float g_bnsum[HID];
__device__ float g_bnsq[HID];
__device__ float g_bnscale[HID];
__device__ float g_bnshift[HID];

// ---------------- CSR build --------------------------------------------------
__global__ void zero_kernel() {
    int i = blockIdx.x * blockDim.x + threadIdx.x;
    if (i < N_NODES) g_deg[i] = 0;
    if (i < HID) { g_bnsum[i] = 0.f; g_bnsq[i] = 0.f; }
}

__global__ void hist_kernel(const int* __restrict__ ei) {
    int e = blockIdx.x * blockDim.x + threadIdx.x;
    if (e < N_EDGES) atomicAdd(&g_deg[ei[N_EDGES + e]], 1);
}

__global__ void scan_chunk_kernel() {
    __shared__ int s[CHUNK];
    int t = threadIdx.x;
    int i = blockIdx.x * CHUNK + t;
    int v = (i < N_NODES) ? g_deg[i] : 0;
    s[t] = v;
    __syncthreads();
    for (int off = 1; off < CHUNK; off <<= 1) {
        int add = (t >= off) ? s[t - off] : 0;
        __syncthreads();
        s[t] += add;
        __syncthreads();
    }
    if (i < N_NODES) g_rowptr[i] = s[t] - v;          // exclusive within chunk
    if (t == CHUNK - 1) g_chunk[blockIdx.x] = s[t];   // chunk total
}

__global__ void scan_tops_kernel() {
    __shared__ int s[256];
    int t = threadIdx.x;
    int v = (t < NCHUNK) ? g_chunk[t] : 0;
    s[t] = v;
    __syncthreads();
    for (int off = 1; off < 256; off <<= 1) {
        int add = (t >= off) ? s[t - off] : 0;
        __syncthreads();
        s[t] += add;
        __syncthreads();
    }
    if (t < NCHUNK) g_chunk[t] = s[t] - v;            // exclusive chunk offsets
}

__global__ void add_off_kernel() {
    int i = blockIdx.x * blockDim.x + threadIdx.x;
    if (i < N_NODES) {
        int rp = g_rowptr[i] + g_chunk[i / CHUNK];
        g_rowptr[i] = rp;
        g_pos[i] = rp;
    }
}

__global__ void fill_kernel(const int* __restrict__ ei) {
    int e = blockIdx.x * blockDim.x + threadIdx.x;
    if (e < N_EDGES) {
        int src = ei[e];
        int dst = ei[N_EDGES + e];
        int p = atomicAdd(&g_pos[dst], 1);
        g_col[p] = src;
    }
}

// ---------------- layer 1: gather + GEMM + L2norm + relu + BN stats ---------
// smem: sW[128*128] | sA[32*128] | sB[128] | sSum[128] | sSq[128]
#define SMEM1 ((HID*HID + NPB*HID + 3*HID) * 4)

__global__ __launch_bounds__(256) void layer1_kernel(
    const float* __restrict__ x,
    const float* __restrict__ w1l,
    const float* __restrict__ w1r,
    const float* __restrict__ b1l)
{
    extern __shared__ float sm[];
    float* sW   = sm;                  // [128][128]: rows 0..63=w1l, 64..127=w1r
    float* sA   = sW + HID * HID;      // [32][128]:  cols 0..63=agg, 64..127=x
    float* sB   = sA + NPB * HID;
    float* sSum = sB + HID;
    float* sSq  = sSum + HID;

    int tx = threadIdx.x;
    for (int i = tx; i < IN_DIM * HID; i += 256) {
        sW[i] = w1l[i];
        sW[IN_DIM * HID + i] = w1r[i];
    }
    if (tx < HID) { sB[tx] = b1l[tx]; sSum[tx] = 0.f; sSq[tx] = 0.f; }

    int warp = tx >> 5, lane = tx & 31;
    int nb = blockIdx.x * NPB;
    const float2* x2 = (const float2*)x;

    // gather: each warp aggregates 4 nodes; lane owns dims {2*lane, 2*lane+1}
    #pragma unroll
    for (int i = 0; i < 4; i++) {
        int nl = warp * 4 + i;
        int n  = nb + nl;
        int d  = g_deg[n];
        int st = g_rowptr[n];
        float ax = 0.f, ay = 0.f;
        int it = 0;
        for (; it + 4 <= d; it += 4) {
            int s0 = g_col[st + it], s1 = g_col[st + it + 1];
            int s2 = g_col[st + it + 2], s3 = g_col[st + it + 3];
            float2 v0 = x2[s0 * 32 + lane];
            float2 v1 = x2[s1 * 32 + lane];
            float2 v2 = x2[s2 * 32 + lane];
            float2 v3 = x2[s3 * 32 + lane];
            ax += v0.x + v1.x + v2.x + v3.x;
            ay += v0.y + v1.y + v2.y + v3.y;
        }
        for (; it < d; it++) {
            int s = g_col[st + it];
            float2 v = x2[s * 32 + lane];
            ax += v.x; ay += v.y;
        }
        float rc = 1.0f / fmaxf((float)d, 1.0f);
        float2 xv = x2[n * 32 + lane];
        float2* row = (float2*)(sA + nl * HID);
        row[lane]      = make_float2(ax * rc, ay * rc);
        row[32 + lane] = xv;
    }
    __syncthreads();

    // GEMM: thread (r,c) computes nodes r*4..+3  x  cols c*4..+3
    int c = tx & 31, r = tx >> 5;
    float acc[4][4];
    #pragma unroll
    for (int i = 0; i < 4; i++)
        #pragma unroll
        for (int j = 0; j < 4; j++) acc[i][j] = sB[c * 4 + j];

    const float* a0 = sA + (r * 4 + 0) * HID;
    const float* a1 = sA + (r * 4 + 1) * HID;
    const float* a2 = sA + (r * 4 + 2) * HID;
    const float* a3 = sA + (r * 4 + 3) * HID;

    #pragma unroll 4
    for (int k = 0; k < HID; k++) {
        float v0 = a0[k], v1 = a1[k], v2 = a2[k], v3 = a3[k];
        float4 w = *(const float4*)(sW + k * HID + c * 4);
        acc[0][0] += v0 * w.x; acc[0][1] += v0 * w.y; acc[0][2] += v0 * w.z; acc[0][3] += v0 * w.w;
        acc[1][0] += v1 * w.x; acc[1][1] += v1 * w.y; acc[1][2] += v1 * w.z; acc[1][3] += v1 * w.w;
        acc[2][0] += v2 * w.x; acc[2][1] += v2 * w.y; acc[2][2] += v2 * w.z; acc[2][3] += v2 * w.w;
        acc[3][0] += v3 * w.x; acc[3][1] += v3 * w.y; acc[3][2] += v3 * w.z; acc[3][3] += v3 * w.w;
    }

    // epilogue: L2-normalize each node row, relu, store h1, BN partial stats
    float lsum[4] = {0, 0, 0, 0}, lsq[4] = {0, 0, 0, 0};
    #pragma unroll
    for (int i = 0; i < 4; i++) {
        float ss = acc[i][0] * acc[i][0] + acc[i][1] * acc[i][1]
                 + acc[i][2] * acc[i][2] + acc[i][3] * acc[i][3];
        for (int o = 16; o; o >>= 1) ss += __shfl_xor_sync(0xffffffffu, ss, o);
        float inv = 1.0f / fmaxf(sqrtf(ss), 1e-12f);
        float4 hv;
        hv.x = fmaxf(acc[i][0] * inv, 0.f);
        hv.y = fmaxf(acc[i][1] * inv, 0.f);
        hv.z = fmaxf(acc[i][2] * inv, 0.f);
        hv.w = fmaxf(acc[i][3] * inv, 0.f);
        int n = nb + r * 4 + i;
        *(float4*)(g_h1 + n * HID + c * 4) = hv;
        lsum[0] += hv.x; lsum[1] += hv.y; lsum[2] += hv.z; lsum[3] += hv.w;
        lsq[0] += hv.x * hv.x; lsq[1] += hv.y * hv.y;
        lsq[2] += hv.z * hv.z; lsq[3] += hv.w * hv.w;
    }
    #pragma unroll
    for (int j = 0; j < 4; j++) {
        atomicAdd(&sSum[c * 4 + j], lsum[j]);
        atomicAdd(&sSq[c * 4 + j], lsq[j]);
    }
    __syncthreads();
    if (tx < HID) {
        atomicAdd(&g_bnsum[tx], sSum[tx]);
        atomicAdd(&g_bnsq[tx], sSq[tx]);
    }
}

// ---------------- BN finalize ----------------
__global__ void bn_finalize_kernel(const float* __restrict__ gamma,
                                   const float* __restrict__ beta)
{
    int j = threadIdx.x;
    if (j < HID) {
        float mean = g_bnsum[j] / (float)N_NODES;
        float var  = g_bnsq[j] / (float)N_NODES - mean * mean;
        float inv  = rsqrtf(var + 1e-5f);
        float sc   = gamma[j] * inv;
        g_bnscale[j] = sc;
        g_bnshift[j] = beta[j] - mean * sc;
    }
}

// ---------------- layer 2: gather(BN fused) + GEMM + L2norm + FC ------------
// smem: sW[256*128] | sA[32*256] | sWfc[128*16] | sB[128] | sSc[128] | sSh[128] | sBfc[16]
#define SMEM2 ((2*HID*HID + NPB*2*HID + HID*OUT_DIM + 3*HID + OUT_DIM) * 4)
#define SH_STRIDE 132

__global__ __launch_bounds__(256) void layer2_kernel(
    const float* __restrict__ w2l,
    const float* __restrict__ b2l,
    const float* __restrict__ w2r,
    const float* __restrict__ wfc,
    const float* __restrict__ bfc,
    float* __restrict__ out)
{
    extern __shared__ float sm[];
    float* sW   = sm;                      // [256][128]: rows 0..127=w2l, 128..255=w2r
    float* sA   = sW + 2 * HID * HID;      // [32][256]
    float* sWfc = sA + NPB * 2 * HID;      // [128][16]
    float* sB   = sWfc + HID * OUT_DIM;
    float* sSc  = sB + HID;
    float* sSh  = sSc + HID;
    float* sBfc = sSh + HID;

    int tx = threadIdx.x;
    for (int i = tx; i < HID * HID; i += 256) {
        sW[i] = w2l[i];
        sW[HID * HID + i] = w2r[i];
    }
    for (int i = tx; i < HID * OUT_DIM; i += 256) sWfc[i] = wfc[i];
    if (tx < HID) { sB[tx] = b2l[tx]; sSc[tx] = g_bnscale[tx]; sSh[tx] = g_bnshift[tx]; }
    if (tx < OUT_DIM) sBfc[tx] = bfc[tx];
    __syncthreads();

    int warp = tx >> 5, lane = tx & 31;
    int nb = blockIdx.x * NPB;
    const float4* h4 = (const float4*)g_h1;
    float4 sc = ((const float4*)sSc)[lane];
    float4 sh = ((const float4*)sSh)[lane];

    // gather: lane owns dims {4*lane .. 4*lane+3}; BN fused
    #pragma unroll
    for (int i = 0; i < 4; i++) {
        int nl = warp * 4 + i;
        int n  = nb + nl;
        int d  = g_deg[n];
        int st = g_rowptr[n];
        float4 acc = make_float4(0.f, 0.f, 0.f, 0.f);
        int it = 0;
        for (; it + 4 <= d; it += 4) {
            int s0 = g_col[st + it], s1 = g_col[st + it + 1];
            int s2 = g_col[st + it + 2], s3 = g_col[st + it + 3];
            float4 v0 = h4[s0 * 32 + lane];
            float4 v1 = h4[s1 * 32 + lane];
            float4 v2 = h4[s2 * 32 + lane];
            float4 v3 = h4[s3 * 32 + lane];
            acc.x += v0.x + v1.x + v2.x + v3.x;
            acc.y += v0.y + v1.y + v2.y + v3.y;
            acc.z += v0.z + v1.z + v2.z + v3.z;
            acc.w += v0.w + v1.w + v2.w + v3.w;
        }
        for (; it < d; it++) {
            int s = g_col[st + it];
            float4 v = h4[s * 32 + lane];
            acc.x += v.x; acc.y += v.y; acc.z += v.z; acc.w += v.w;
        }
        float rc = 1.0f / fmaxf((float)d, 1.0f);
        float flag = (d > 0) ? 1.0f : 0.0f;
        // agg of BN-ed features: sc * mean(h) + sh * [deg>0]
        float4 ag;
        ag.x = sc.x * acc.x * rc + sh.x * flag;
        ag.y = sc.y * acc.y * rc + sh.y * flag;
        ag.z = sc.z * acc.z * rc + sh.z * flag;
        ag.w = sc.w * acc.w * rc + sh.w * flag;
        ((float4*)(sA + nl * 2 * HID))[lane] = ag;
        // self features (BN always applied)
        float4 hv = h4[n * 32 + lane];
        float4 lr;
        lr.x = sc.x * hv.x + sh.x;
        lr.y = sc.y * hv.y + sh.y;
        lr.z = sc.z * hv.z + sh.z;
        lr.w = sc.w * hv.w + sh.w;
        ((float4*)(sA + nl * 2 * HID + HID))[lane] = lr;
    }
    __syncthreads();

    // GEMM K=256
    int c = tx & 31, r = tx >> 5;
    float acc[4][4];
    #pragma unroll
    for (int i = 0; i < 4; i++)
        #pragma unroll
        for (int j = 0; j < 4; j++) acc[i][j] = sB[c * 4 + j];

    const float* a0 = sA + (r * 4 + 0) * 2 * HID;
    const float* a1 = sA + (r * 4 + 1) * 2 * HID;
    const float* a2 = sA + (r * 4 + 2) * 2 * HID;
    const float* a3 = sA + (r * 4 + 3) * 2 * HID;

    #pragma unroll 4
    for (int k = 0; k < 2 * HID; k++) {
        float v0 = a0[k], v1 = a1[k], v2 = a2[k], v3 = a3[k];
        float4 w = *(const float4*)(sW + k * HID + c * 4);
        acc[0][0] += v0 * w.x; acc[0][1] += v0 * w.y; acc[0][2] += v0 * w.z; acc[0][3] += v0 * w.w;
        acc[1][0] += v1 * w.x; acc[1][1] += v1 * w.y; acc[1][2] += v1 * w.z; acc[1][3] += v1 * w.w;
        acc[2][0] += v2 * w.x; acc[2][1] += v2 * w.y; acc[2][2] += v2 * w.z; acc[2][3] += v2 * w.w;
        acc[3][0] += v3 * w.x; acc[3][1] += v3 * w.y; acc[3][2] += v3 * w.z; acc[3][3] += v3 * w.w;
    }

    // L2-normalize each node row (no relu here)
    #pragma unroll
    for (int i = 0; i < 4; i++) {
        float ss = acc[i][0] * acc[i][0] + acc[i][1] * acc[i][1]
                 + acc[i][2] * acc[i][2] + acc[i][3] * acc[i][3];
        for (int o = 16; o; o >>= 1) ss += __shfl_xor_sync(0xffffffffu, ss, o);
        float inv = 1.0f / fmaxf(sqrtf(ss), 1e-12f);
        acc[i][0] *= inv; acc[i][1] *= inv; acc[i][2] *= inv; acc[i][3] *= inv;
    }
    __syncthreads();   // everyone done reading sA before we reuse it as sH

    float* sH = sA;    // [32][SH_STRIDE]
    #pragma unroll
    for (int i = 0; i < 4; i++) {
        float4 hv = make_float4(acc[i][0], acc[i][1], acc[i][2], acc[i][3]);
        *(float4*)(sH + (r * 4 + i) * SH_STRIDE + c * 4) = hv;
    }
    __syncthreads();

    // FC: 32 nodes x 16 outputs = 512 values; 2 per thread
    int nl = tx >> 3;           // node 0..31
    int og = tx & 7;            // output pair group
    int o0 = og * 2, o1 = o0 + 1;
    float y0 = sBfc[o0], y1 = sBfc[o1];
    const float* h = sH + nl * SH_STRIDE;
    #pragma unroll 4
    for (int j = 0; j < HID; j++) {
        float hv = h[j];
        y0 += hv * sWfc[j * OUT_DIM + o0];
        y1 += hv * sWfc[j * OUT_DIM + o1];
    }
    int n = nb + nl;
    out[n * OUT_DIM + o0] = y0;
    out[n * OUT_DIM + o1] = y1;
}

// ---------------- launch ----------------------------------------------------
extern "C" void kernel_launch(void* const* d_in, const int* in_sizes, int n_in,
                              void* d_out, int out_size)
{
    const float* x     = (const float*)d_in[0];
    const int*   ei    = (const int*)d_in[1];
    const float* w1l   = (const float*)d_in[2];
    const float* b1l   = (const float*)d_in[3];
    const float* w1r   = (const float*)d_in[4];
    const float* gamma = (const float*)d_in[5];
    const float* beta  = (const float*)d_in[6];
    const float* w2l   = (const float*)d_in[7];
    const float* b2l   = (const float*)d_in[8];
    const float* w2r   = (const float*)d_in[9];
    const float* wfc   = (const float*)d_in[10];
    const float* bfc   = (const float*)d_in[11];
    float* out = (float*)d_out;

    cudaFuncSetAttribute(layer1_kernel, cudaFuncAttributeMaxDynamicSharedMemorySize, SMEM1);
    cudaFuncSetAttribute(layer2_kernel, cudaFuncAttributeMaxDynamicSharedMemorySize, SMEM2);

    int ng = (N_NODES + 255) / 256;     // 391
    int eg = (N_EDGES + 255) / 256;     // 6250
    int lg = N_NODES / NPB;             // 3125

    zero_kernel<<<ng, 256>>>();
    hist_kernel<<<eg, 256>>>(ei);
    scan_chunk_kernel<<<NCHUNK, CHUNK>>>();
    scan_tops_kernel<<<1, 256>>>();
    add_off_kernel<<<ng, 256>>>();
    fill_kernel<<<eg, 256>>>(ei);
    layer1_kernel<<<lg, 256, SMEM1>>>(x, w1l, w1r, b1l);
    bn_finalize_kernel<<<1, 128>>>(gamma, beta);
    layer2_kernel<<<lg, 256, SMEM2>>>(w2l, b2l, w2r, wfc, bfc, out);
}

// round 3
// speedup vs baseline: 1.0653x; 1.0653x over previous
#include <cuda_runtime.h>

typedef unsigned long long ull;

#define N_NODES 100000
#define N_EDGES 1600000
#define IN_DIM  64
#define HID     128
#define OUT_DIM 16
#define NPB     32          // nodes per block in layer kernels
#define CHUNK   512
#define NCHUNK  ((N_NODES + CHUNK - 1) / CHUNK)   // 196

// ---------------- scratch (device globals; no allocation allowed) ----------
__device__ int   g_deg[N_NODES];
__device__ int   g_rowptr[N_NODES];
__device__ int   g_pos[N_NODES];
__device__ int   g_col[N_EDGES];
__device__ int   g_chunk[NCHUNK];
__device__ float g_h1[N_NODES * HID];     // relu(normalize(layer1 out))
__device__ float g_bnsum[HID];
__device__ float g_bnsq[HID];
__device__ float g_bnscale[HID];
__device__ float g_bnshift[HID];

// ---------------- packed f32x2 helpers (Blackwell FFMA2) --------------------
__device__ __forceinline__ ull pack2(float v) {
    ull r; asm("mov.b64 %0, {%1, %1};" : "=l"(r) : "f"(v)); return r;
}
__device__ __forceinline__ ull packxy(float x, float y) {
    ull r; asm("mov.b64 %0, {%1, %2};" : "=l"(r) : "f"(x), "f"(y)); return r;
}
__device__ __forceinline__ float2 unpack2(ull v) {
    float2 f; asm("mov.b64 {%0, %1}, %2;" : "=f"(f.x), "=f"(f.y) : "l"(v)); return f;
}
__device__ __forceinline__ void fma2(ull& d, ull a, ull b) {
    asm("fma.rn.f32x2 %0, %1, %2, %0;" : "+l"(d) : "l"(a), "l"(b));
}

// ---------------- CSR build --------------------------------------------------
__global__ void zero_kernel() {
    int i = blockIdx.x * blockDim.x + threadIdx.x;
    if (i < N_NODES) g_deg[i] = 0;
    if (i < HID) { g_bnsum[i] = 0.f; g_bnsq[i] = 0.f; }
}

__global__ void hist_kernel(const int* __restrict__ ei) {
    int e = blockIdx.x * blockDim.x + threadIdx.x;
    if (e < N_EDGES) atomicAdd(&g_deg[ei[N_EDGES + e]], 1);
}

__global__ void scan_chunk_kernel() {
    __shared__ int s[CHUNK];
    int t = threadIdx.x;
    int i = blockIdx.x * CHUNK + t;
    int v = (i < N_NODES) ? g_deg[i] : 0;
    s[t] = v;
    __syncthreads();
    for (int off = 1; off < CHUNK; off <<= 1) {
        int add = (t >= off) ? s[t - off] : 0;
        __syncthreads();
        s[t] += add;
        __syncthreads();
    }
    if (i < N_NODES) g_rowptr[i] = s[t] - v;          // exclusive within chunk
    if (t == CHUNK - 1) g_chunk[blockIdx.x] = s[t];   // chunk total
}

__global__ void scan_tops_kernel() {
    __shared__ int s[256];
    int t = threadIdx.x;
    int v = (t < NCHUNK) ? g_chunk[t] : 0;
    s[t] = v;
    __syncthreads();
    for (int off = 1; off < 256; off <<= 1) {
        int add = (t >= off) ? s[t - off] : 0;
        __syncthreads();
        s[t] += add;
        __syncthreads();
    }
    if (t < NCHUNK) g_chunk[t] = s[t] - v;            // exclusive chunk offsets
}

__global__ void add_off_kernel() {
    int i = blockIdx.x * blockDim.x + threadIdx.x;
    if (i < N_NODES) {
        int rp = g_rowptr[i] + g_chunk[i / CHUNK];
        g_rowptr[i] = rp;
        g_pos[i] = rp;
    }
}

__global__ void fill_kernel(const int* __restrict__ ei) {
    int e = blockIdx.x * blockDim.x + threadIdx.x;
    if (e < N_EDGES) {
        int src = ei[e];
        int dst = ei[N_EDGES + e];
        int p = atomicAdd(&g_pos[dst], 1);
        g_col[p] = src;
    }
}

// ---------------- layer 1: gather + GEMM + L2norm + relu + BN stats ---------
// smem: sW[128*128] | sA[32*128] | sB[128] | sSum[128] | sSq[128]
#define SMEM1 ((HID*HID + NPB*HID + 3*HID) * 4)

__global__ __launch_bounds__(128) void layer1_kernel(
    const float* __restrict__ x,
    const float* __restrict__ w1l,
    const float* __restrict__ w1r,
    const float* __restrict__ b1l)
{
    extern __shared__ float sm[];
    float* sW   = sm;                  // [128][128]: rows 0..63=w1l, 64..127=w1r
    float* sA   = sW + HID * HID;      // [32][128]:  cols 0..63=agg, 64..127=x
    float* sB   = sA + NPB * HID;
    float* sSum = sB + HID;
    float* sSq  = sSum + HID;

    int tx = threadIdx.x;
    const float4* wl4 = (const float4*)w1l;
    const float4* wr4 = (const float4*)w1r;
    #pragma unroll
    for (int i = tx; i < IN_DIM * HID / 4; i += 128) {
        ((float4*)sW)[i] = wl4[i];
        ((float4*)sW)[IN_DIM * HID / 4 + i] = wr4[i];
    }
    sB[tx] = b1l[tx];          // tx < 128 == HID
    sSum[tx] = 0.f;
    sSq[tx] = 0.f;

    int warp = tx >> 5, lane = tx & 31;
    int nb = blockIdx.x * NPB;
    const float2* x2 = (const float2*)x;

    // gather: each warp aggregates 8 nodes; lane owns dims {2*lane, 2*lane+1}
    #pragma unroll
    for (int i = 0; i < 8; i++) {
        int nl = warp * 8 + i;
        int n  = nb + nl;
        int d  = g_deg[n];
        int st = g_rowptr[n];
        float ax = 0.f, ay = 0.f;
        int it = 0;
        for (; it + 8 <= d; it += 8) {
            int s0 = g_col[st + it + 0], s1 = g_col[st + it + 1];
            int s2 = g_col[st + it + 2], s3 = g_col[st + it + 3];
            int s4 = g_col[st + it + 4], s5 = g_col[st + it + 5];
            int s6 = g_col[st + it + 6], s7 = g_col[st + it + 7];
            float2 v0 = x2[s0 * 32 + lane];
            float2 v1 = x2[s1 * 32 + lane];
            float2 v2 = x2[s2 * 32 + lane];
            float2 v3 = x2[s3 * 32 + lane];
            float2 v4 = x2[s4 * 32 + lane];
            float2 v5 = x2[s5 * 32 + lane];
            float2 v6 = x2[s6 * 32 + lane];
            float2 v7 = x2[s7 * 32 + lane];
            ax += ((v0.x + v1.x) + (v2.x + v3.x)) + ((v4.x + v5.x) + (v6.x + v7.x));
            ay += ((v0.y + v1.y) + (v2.y + v3.y)) + ((v4.y + v5.y) + (v6.y + v7.y));
        }
        for (; it < d; it++) {
            int s = g_col[st + it];
            float2 v = x2[s * 32 + lane];
            ax += v.x; ay += v.y;
        }
        float rc = 1.0f / fmaxf((float)d, 1.0f);
        float2 xv = x2[n * 32 + lane];
        float2* row = (float2*)(sA + nl * HID);
        row[lane]      = make_float2(ax * rc, ay * rc);
        row[32 + lane] = xv;
    }
    __syncthreads();

    // GEMM: thread (r,c) computes 4 nodes (r*4..+3) x 8 cols (c*8..+7) via FFMA2
    int c = tx & 15, r = tx >> 4;
    ull acc[4][4];
    #pragma unroll
    for (int j = 0; j < 4; j++) {
        ull b = packxy(sB[c * 8 + 2 * j], sB[c * 8 + 2 * j + 1]);
        acc[0][j] = b; acc[1][j] = b; acc[2][j] = b; acc[3][j] = b;
    }

    const float* a0 = sA + (r * 4 + 0) * HID;
    const float* a1 = sA + (r * 4 + 1) * HID;
    const float* a2 = sA + (r * 4 + 2) * HID;
    const float* a3 = sA + (r * 4 + 3) * HID;

    #pragma unroll 4
    for (int k = 0; k < HID; k++) {
        ull va0 = pack2(a0[k]);
        ull va1 = pack2(a1[k]);
        ull va2 = pack2(a2[k]);
        ull va3 = pack2(a3[k]);
        ulonglong2 wa = *(const ulonglong2*)(sW + k * HID + c * 8);
        ulonglong2 wb = *(const ulonglong2*)(sW + k * HID + c * 8 + 4);
        fma2(acc[0][0], va0, wa.x); fma2(acc[0][1], va0, wa.y);
        fma2(acc[0][2], va0, wb.x); fma2(acc[0][3], va0, wb.y);
        fma2(acc[1][0], va1, wa.x); fma2(acc[1][1], va1, wa.y);
        fma2(acc[1][2], va1, wb.x); fma2(acc[1][3], va1, wb.y);
        fma2(acc[2][0], va2, wa.x); fma2(acc[2][1], va2, wa.y);
        fma2(acc[2][2], va2, wb.x); fma2(acc[2][3], va2, wb.y);
        fma2(acc[3][0], va3, wa.x); fma2(acc[3][1], va3, wa.y);
        fma2(acc[3][2], va3, wb.x); fma2(acc[3][3], va3, wb.y);
    }

    // epilogue: L2-normalize each node row, relu, store h1, BN partial stats
    float lsum[8] = {0, 0, 0, 0, 0, 0, 0, 0};
    float lsq[8]  = {0, 0, 0, 0, 0, 0, 0, 0};
    #pragma unroll
    for (int i = 0; i < 4; i++) {
        float2 p0 = unpack2(acc[i][0]);
        float2 p1 = unpack2(acc[i][1]);
        float2 p2 = unpack2(acc[i][2]);
        float2 p3 = unpack2(acc[i][3]);
        float ss = (p0.x * p0.x + p0.y * p0.y) + (p1.x * p1.x + p1.y * p1.y)
                 + (p2.x * p2.x + p2.y * p2.y) + (p3.x * p3.x + p3.y * p3.y);
        // reduce over the 16 col-groups (lane bits 0..3)
        for (int o = 8; o; o >>= 1) ss += __shfl_xor_sync(0xffffffffu, ss, o);
        float inv = 1.0f / fmaxf(sqrtf(ss), 1e-12f);
        float h0 = fmaxf(p0.x * inv, 0.f), h1v = fmaxf(p0.y * inv, 0.f);
        float h2 = fmaxf(p1.x * inv, 0.f), h3 = fmaxf(p1.y * inv, 0.f);
        float h4 = fmaxf(p2.x * inv, 0.f), h5 = fmaxf(p2.y * inv, 0.f);
        float h6 = fmaxf(p3.x * inv, 0.f), h7 = fmaxf(p3.y * inv, 0.f);
        int n = nb + r * 4 + i;
        *(float4*)(g_h1 + n * HID + c * 8)     = make_float4(h0, h1v, h2, h3);
        *(float4*)(g_h1 + n * HID + c * 8 + 4) = make_float4(h4, h5, h6, h7);
        lsum[0] += h0; lsum[1] += h1v; lsum[2] += h2; lsum[3] += h3;
        lsum[4] += h4; lsum[5] += h5;  lsum[6] += h6; lsum[7] += h7;
        lsq[0] += h0 * h0; lsq[1] += h1v * h1v; lsq[2] += h2 * h2; lsq[3] += h3 * h3;
        lsq[4] += h4 * h4; lsq[5] += h5 * h5;   lsq[6] += h6 * h6; lsq[7] += h7 * h7;
    }
    #pragma unroll
    for (int j = 0; j < 8; j++) {
        atomicAdd(&sSum[c * 8 + j], lsum[j]);
        atomicAdd(&sSq[c * 8 + j], lsq[j]);
    }
    __syncthreads();
    atomicAdd(&g_bnsum[tx], sSum[tx]);
    atomicAdd(&g_bnsq[tx], sSq[tx]);
}

// ---------------- BN finalize ----------------
__global__ void bn_finalize_kernel(const float* __restrict__ gamma,
                                   const float* __restrict__ beta)
{
    int j = threadIdx.x;
    if (j < HID) {
        float mean = g_bnsum[j] / (float)N_NODES;
        float var  = g_bnsq[j] / (float)N_NODES - mean * mean;
        float inv  = rsqrtf(var + 1e-5f);
        float sc   = gamma[j] * inv;
        g_bnscale[j] = sc;
        g_bnshift[j] = beta[j] - mean * sc;
    }
}

// ---------------- layer 2: gather(BN fused) + GEMM(K-streamed W) + L2norm + FC
// smem: sW[128*128] (streamed halves) | sA[32*256] | sWfc[128*16] | sB[128] |
//       sSc[128] | sSh[128] | sBfc[16]
#define SMEM2 ((HID*HID + NPB*2*HID + HID*OUT_DIM + 3*HID + OUT_DIM) * 4)
#define SH_STRIDE 132

__global__ __launch_bounds__(128) void layer2_kernel(
    const float* __restrict__ w2l,
    const float* __restrict__ b2l,
    const float* __restrict__ w2r,
    const float* __restrict__ wfc,
    const float* __restrict__ bfc,
    float* __restrict__ out)
{
    extern __shared__ float sm[];
    float* sW   = sm;                      // [128][128] streamed: w2l then w2r
    float* sA   = sW + HID * HID;          // [32][256]
    float* sWfc = sA + NPB * 2 * HID;      // [128][16]
    float* sB   = sWfc + HID * OUT_DIM;
    float* sSc  = sB + HID;
    float* sSh  = sSc + HID;
    float* sBfc = sSh + HID;

    int tx = threadIdx.x;
    const float4* wl4 = (const float4*)w2l;
    #pragma unroll
    for (int i = tx; i < HID * HID / 4; i += 128)
        ((float4*)sW)[i] = wl4[i];
    #pragma unroll
    for (int i = tx; i < HID * OUT_DIM / 4; i += 128)
        ((float4*)sWfc)[i] = ((const float4*)wfc)[i];
    sB[tx]  = b2l[tx];
    sSc[tx] = g_bnscale[tx];
    sSh[tx] = g_bnshift[tx];
    if (tx < OUT_DIM) sBfc[tx] = bfc[tx];
    __syncthreads();

    int warp = tx >> 5, lane = tx & 31;
    int nb = blockIdx.x * NPB;
    const float4* h4 = (const float4*)g_h1;
    float4 sc = ((const float4*)sSc)[lane];
    float4 sh = ((const float4*)sSh)[lane];

    // gather: each warp 8 nodes; lane owns dims {4*lane..4*lane+3}; BN fused
    #pragma unroll
    for (int i = 0; i < 8; i++) {
        int nl = warp * 8 + i;
        int n  = nb + nl;
        int d  = g_deg[n];
        int st = g_rowptr[n];
        float4 acc = make_float4(0.f, 0.f, 0.f, 0.f);
        int it = 0;
        for (; it + 8 <= d; it += 8) {
            int s0 = g_col[st + it + 0], s1 = g_col[st + it + 1];
            int s2 = g_col[st + it + 2], s3 = g_col[st + it + 3];
            int s4 = g_col[st + it + 4], s5 = g_col[st + it + 5];
            int s6 = g_col[st + it + 6], s7 = g_col[st + it + 7];
            float4 v0 = h4[s0 * 32 + lane];
            float4 v1 = h4[s1 * 32 + lane];
            float4 v2 = h4[s2 * 32 + lane];
            float4 v3 = h4[s3 * 32 + lane];
            float4 v4 = h4[s4 * 32 + lane];
            float4 v5 = h4[s5 * 32 + lane];
            float4 v6 = h4[s6 * 32 + lane];
            float4 v7 = h4[s7 * 32 + lane];
            acc.x += ((v0.x + v1.x) + (v2.x + v3.x)) + ((v4.x + v5.x) + (v6.x + v7.x));
            acc.y += ((v0.y + v1.y) + (v2.y + v3.y)) + ((v4.y + v5.y) + (v6.y + v7.y));
            acc.z += ((v0.z + v1.z) + (v2.z + v3.z)) + ((v4.z + v5.z) + (v6.z + v7.z));
            acc.w += ((v0.w + v1.w) + (v2.w + v3.w)) + ((v4.w + v5.w) + (v6.w + v7.w));
        }
        for (; it < d; it++) {
            int s = g_col[st + it];
            float4 v = h4[s * 32 + lane];
            acc.x += v.x; acc.y += v.y; acc.z += v.z; acc.w += v.w;
        }
        float rc = 1.0f / fmaxf((float)d, 1.0f);
        float flag = (d > 0) ? 1.0f : 0.0f;
        float4 ag;
        ag.x = sc.x * acc.x * rc + sh.x * flag;
        ag.y = sc.y * acc.y * rc + sh.y * flag;
        ag.z = sc.z * acc.z * rc + sh.z * flag;
        ag.w = sc.w * acc.w * rc + sh.w * flag;
        ((float4*)(sA + nl * 2 * HID))[lane] = ag;
        float4 hv = h4[n * 32 + lane];
        float4 lr;
        lr.x = sc.x * hv.x + sh.x;
        lr.y = sc.y * hv.y + sh.y;
        lr.z = sc.z * hv.z + sh.z;
        lr.w = sc.w * hv.w + sh.w;
        ((float4*)(sA + nl * 2 * HID + HID))[lane] = lr;
    }
    __syncthreads();

    // GEMM K=256, weights streamed in two K=128 halves
    int c = tx & 15, r = tx >> 4;
    ull acc[4][4];
    #pragma unroll
    for (int j = 0; j < 4; j++) {
        ull b = packxy(sB[c * 8 + 2 * j], sB[c * 8 + 2 * j + 1]);
        acc[0][j] = b; acc[1][j] = b; acc[2][j] = b; acc[3][j] = b;
    }

    #pragma unroll
    for (int pass = 0; pass < 2; pass++) {
        if (pass == 1) {
            __syncthreads();   // pass-0 GEMM done before overwriting sW
            const float4* wr4 = (const float4*)w2r;
            #pragma unroll
            for (int i = tx; i < HID * HID / 4; i += 128)
                ((float4*)sW)[i] = wr4[i];
            __syncthreads();
        }
        const float* a0 = sA + (r * 4 + 0) * 2 * HID + pass * HID;
        const float* a1 = sA + (r * 4 + 1) * 2 * HID + pass * HID;
        const float* a2 = sA + (r * 4 + 2) * 2 * HID + pass * HID;
        const float* a3 = sA + (r * 4 + 3) * 2 * HID + pass * HID;

        #pragma unroll 4
        for (int k = 0; k < HID; k++) {
            ull va0 = pack2(a0[k]);
            ull va1 = pack2(a1[k]);
            ull va2 = pack2(a2[k]);
            ull va3 = pack2(a3[k]);
            ulonglong2 wa = *(const ulonglong2*)(sW + k * HID + c * 8);
            ulonglong2 wb = *(const ulonglong2*)(sW + k * HID + c * 8 + 4);
            fma2(acc[0][0], va0, wa.x); fma2(acc[0][1], va0, wa.y);
            fma2(acc[0][2], va0, wb.x); fma2(acc[0][3], va0, wb.y);
            fma2(acc[1][0], va1, wa.x); fma2(acc[1][1], va1, wa.y);
            fma2(acc[1][2], va1, wb.x); fma2(acc[1][3], va1, wb.y);
            fma2(acc[2][0], va2, wa.x); fma2(acc[2][1], va2, wa.y);
            fma2(acc[2][2], va2, wb.x); fma2(acc[2][3], va2, wb.y);
            fma2(acc[3][0], va3, wa.x); fma2(acc[3][1], va3, wa.y);
            fma2(acc[3][2], va3, wb.x); fma2(acc[3][3], va3, wb.y);
        }
    }

    // L2-normalize each node row (no relu)
    float hreg[4][8];
    #pragma unroll
    for (int i = 0; i < 4; i++) {
        float2 p0 = unpack2(acc[i][0]);
        float2 p1 = unpack2(acc[i][1]);
        float2 p2 = unpack2(acc[i][2]);
        float2 p3 = unpack2(acc[i][3]);
        float ss = (p0.x * p0.x + p0.y * p0.y) + (p1.x * p1.x + p1.y * p1.y)
                 + (p2.x * p2.x + p2.y * p2.y) + (p3.x * p3.x + p3.y * p3.y);
        for (int o = 8; o; o >>= 1) ss += __shfl_xor_sync(0xffffffffu, ss, o);
        float inv = 1.0f / fmaxf(sqrtf(ss), 1e-12f);
        hreg[i][0] = p0.x * inv; hreg[i][1] = p0.y * inv;
        hreg[i][2] = p1.x * inv; hreg[i][3] = p1.y * inv;
        hreg[i][4] = p2.x * inv; hreg[i][5] = p2.y * inv;
        hreg[i][6] = p3.x * inv; hreg[i][7] = p3.y * inv;
    }
    __syncthreads();   // all warps done reading sA before reuse as sH

    float* sH = sA;    // [32][SH_STRIDE]
    #pragma unroll
    for (int i = 0; i < 4; i++) {
        float* row = sH + (r * 4 + i) * SH_STRIDE + c * 8;
        *(float4*)(row)     = make_float4(hreg[i][0], hreg[i][1], hreg[i][2], hreg[i][3]);
        *(float4*)(row + 4) = make_float4(hreg[i][4], hreg[i][5], hreg[i][6], hreg[i][7]);
    }
    __syncthreads();

    // FC: 32 nodes x 16 outputs = 512 values; 4 per thread
    int nl = tx >> 2;           // node 0..31
    int q  = tx & 3;            // output quad
    float4 y = *(const float4*)(sBfc + q * 4);
    const float* h = sH + nl * SH_STRIDE;
    #pragma unroll 4
    for (int j = 0; j < HID; j++) {
        float hv = h[j];
        float4 w = *(const float4*)(sWfc + j * OUT_DIM + q * 4);
        y.x += hv * w.x; y.y += hv * w.y; y.z += hv * w.z; y.w += hv * w.w;
    }
    *(float4*)(out + (nb + nl) * OUT_DIM + q * 4) = y;
}

// ---------------- launch ----------------------------------------------------
extern "C" void kernel_launch(void* const* d_in, const int* in_sizes, int n_in,
                              void* d_out, int out_size)
{
    const float* x     = (const float*)d_in[0];
    const int*   ei    = (const int*)d_in[1];
    const float* w1l   = (const float*)d_in[2];
    const float* b1l   = (const float*)d_in[3];
    const float* w1r   = (const float*)d_in[4];
    const float* gamma = (const float*)d_in[5];
    const float* beta  = (const float*)d_in[6];
    const float* w2l   = (const float*)d_in[7];
    const float* b2l   = (const float*)d_in[8];
    const float* w2r   = (const float*)d_in[9];
    const float* wfc   = (const float*)d_in[10];
    const float* bfc   = (const float*)d_in[11];
    float* out = (float*)d_out;

    cudaFuncSetAttribute(layer1_kernel, cudaFuncAttributeMaxDynamicSharedMemorySize, SMEM1);
    cudaFuncSetAttribute(layer2_kernel, cudaFuncAttributeMaxDynamicSharedMemorySize, SMEM2);

    int ng = (N_NODES + 255) / 256;     // 391
    int eg = (N_EDGES + 255) / 256;     // 6250
    int lg = N_NODES / NPB;             // 3125

    zero_kernel<<<ng, 256>>>();
    hist_kernel<<<eg, 256>>>(ei);
    scan_chunk_kernel<<<NCHUNK, CHUNK>>>();
    scan_tops_kernel<<<1, 256>>>();
    add_off_kernel<<<ng, 256>>>();
    fill_kernel<<<eg, 256>>>(ei);
    layer1_kernel<<<lg, 128, SMEM1>>>(x, w1l, w1r, b1l);
    bn_finalize_kernel<<<1, 128>>>(gamma, beta);
    layer2_kernel<<<lg, 128, SMEM2>>>(w2l, b2l, w2r, wfc, bfc, out);
}

// round 12
// speedup vs baseline: 1.3384x; 1.2563x over previous
#include <cuda_runtime.h>

typedef unsigned long long ull;

#define N_NODES 100000
#define N_EDGES 1600000
#define IN_DIM  64
#define HID     128
#define OUT_DIM 16
#define MT      128         // GEMM M-tile
#define CHUNK   512
#define NCHUNK  ((N_NODES + CHUNK - 1) / CHUNK)   // 196

// ---------------- scratch (device globals; no allocation allowed) ----------
__device__ __align__(16) int   g_deg[N_NODES];
__device__ __align__(16) int   g_rowptr[N_NODES];
__device__ __align__(16) int   g_pos[N_NODES];
__device__ __align__(16) int   g_col[N_EDGES];
__device__ __align__(16) int   g_chunk[NCHUNK];
__device__ __align__(16) float g_agg1[N_NODES * IN_DIM];
__device__ __align__(16) float g_h1[N_NODES * HID];       // relu(normalize(l1))
__device__ __align__(16) float g_agg2[N_NODES * HID];     // BN'ed neighbor mean
__device__ __align__(16) float g_bnsum[HID];
__device__ __align__(16) float g_bnsq[HID];
__device__ __align__(16) float g_bnscale[HID];
__device__ __align__(16) float g_bnshift[HID];

// ---------------- packed f32x2 helpers --------------------------------------
__device__ __forceinline__ ull pack2(float v) {
    ull r; asm("mov.b64 %0, {%1, %1};" : "=l"(r) : "f"(v)); return r;
}
__device__ __forceinline__ float2 unpack2(ull v) {
    float2 f; asm("mov.b64 {%0, %1}, %2;" : "=f"(f.x), "=f"(f.y) : "l"(v)); return f;
}
__device__ __forceinline__ void fma2(ull& d, ull a, ull b) {
    asm("fma.rn.f32x2 %0, %1, %2, %0;" : "+l"(d) : "l"(a), "l"(b));
}

// ---------------- CSR build --------------------------------------------------
__global__ void zero_kernel() {
    int i = blockIdx.x * blockDim.x + threadIdx.x;
    if (i < N_NODES) g_deg[i] = 0;
    if (i < HID) { g_bnsum[i] = 0.f; g_bnsq[i] = 0.f; }
}

__global__ void hist_kernel(const int* __restrict__ ei) {
    int e = blockIdx.x * blockDim.x + threadIdx.x;
    if (e < N_EDGES) atomicAdd(&g_deg[ei[N_EDGES + e]], 1);
}

__global__ void scan_chunk_kernel() {
    __shared__ int s[CHUNK];
    int t = threadIdx.x;
    int i = blockIdx.x * CHUNK + t;
    int v = (i < N_NODES) ? g_deg[i] : 0;
    s[t] = v;
    __syncthreads();
    for (int off = 1; off < CHUNK; off <<= 1) {
        int add = (t >= off) ? s[t - off] : 0;
        __syncthreads();
        s[t] += add;
        __syncthreads();
    }
    if (i < N_NODES) g_rowptr[i] = s[t] - v;
    if (t == CHUNK - 1) g_chunk[blockIdx.x] = s[t];
}

__global__ void scan_tops_kernel() {
    __shared__ int s[256];
    int t = threadIdx.x;
    int v = (t < NCHUNK) ? g_chunk[t] : 0;
    s[t] = v;
    __syncthreads();
    for (int off = 1; off < 256; off <<= 1) {
        int add = (t >= off) ? s[t - off] : 0;
        __syncthreads();
        s[t] += add;
        __syncthreads();
    }
    if (t < NCHUNK) g_chunk[t] = s[t] - v;
}

__global__ void add_off_kernel() {
    int i = blockIdx.x * blockDim.x + threadIdx.x;
    if (i < N_NODES) {
        int rp = g_rowptr[i] + g_chunk[i / CHUNK];
        g_rowptr[i] = rp;
        g_pos[i] = rp;
    }
}

__global__ void fill_kernel(const int* __restrict__ ei) {
    int e = blockIdx.x * blockDim.x + threadIdx.x;
    if (e < N_EDGES) {
        int src = ei[e];
        int dst = ei[N_EDGES + e];
        int p = atomicAdd(&g_pos[dst], 1);
        g_col[p] = src;
    }
}

// ---------------- gather 1: warp per node, mean of x[neighbors] -------------
__global__ __launch_bounds__(256) void gather1_kernel(const float* __restrict__ x) {
    int warp = threadIdx.x >> 5, lane = threadIdx.x & 31;
    int n = blockIdx.x * 8 + warp;
    if (n >= N_NODES) return;
    int d = g_deg[n], st = g_rowptr[n];
    const float2* x2 = (const float2*)x;
    float ax = 0.f, ay = 0.f;
    for (int base = 0; base < d; base += 32) {
        int m = min(d - base, 32);
        int ci = (lane < m) ? g_col[st + base + lane] : 0;
        int j = 0;
        for (; j + 4 <= m; j += 4) {
            int s0 = __shfl_sync(0xffffffffu, ci, j);
            int s1 = __shfl_sync(0xffffffffu, ci, j + 1);
            int s2 = __shfl_sync(0xffffffffu, ci, j + 2);
            int s3 = __shfl_sync(0xffffffffu, ci, j + 3);
            float2 v0 = x2[s0 * 32 + lane];
            float2 v1 = x2[s1 * 32 + lane];
            float2 v2 = x2[s2 * 32 + lane];
            float2 v3 = x2[s3 * 32 + lane];
            ax += (v0.x + v1.x) + (v2.x + v3.x);
            ay += (v0.y + v1.y) + (v2.y + v3.y);
        }
        for (; j < m; j++) {
            int s = __shfl_sync(0xffffffffu, ci, j);
            float2 v = x2[s * 32 + lane];
            ax += v.x; ay += v.y;
        }
    }
    float rc = 1.0f / fmaxf((float)d, 1.0f);
    ((float2*)g_agg1)[n * 32 + lane] = make_float2(ax * rc, ay * rc);
}

// ---------------- GEMM 1: [agg|x] @ [w1l;w1r] + b, L2norm, relu, BN stats ---
#define KS1 132
#define SMEMG1 ((HID*HID + MT*KS1 + 3*HID) * 4)

__global__ __launch_bounds__(256) void gemm1_kernel(
    const float* __restrict__ x,
    const float* __restrict__ w1l,
    const float* __restrict__ w1r,
    const float* __restrict__ b1l)
{
    extern __shared__ float sm[];
    float* sW   = sm;                  // [128][128]: rows 0..63=w1l, 64..127=w1r
    float* sA   = sW + HID * HID;      // [128][132]
    float* sB   = sA + MT * KS1;
    float* sSum = sB + HID;
    float* sSq  = sSum + HID;

    int tx = threadIdx.x;
    for (int i = tx; i < IN_DIM * HID / 4; i += 256) {
        ((float4*)sW)[i] = ((const float4*)w1l)[i];
        ((float4*)sW)[IN_DIM * HID / 4 + i] = ((const float4*)w1r)[i];
    }
    if (tx < HID) { sB[tx] = b1l[tx]; sSum[tx] = 0.f; sSq[tx] = 0.f; }

    int nb = blockIdx.x * MT;
    for (int i = tx; i < MT * 16; i += 256) {
        int row = i >> 4, q = i & 15;
        int n = nb + row;
        float4 va = make_float4(0.f, 0.f, 0.f, 0.f), vx = va;
        if (n < N_NODES) {
            va = ((const float4*)g_agg1)[n * 16 + q];
            vx = ((const float4*)x)[n * 16 + q];
        }
        *(float4*)(sA + row * KS1 + q * 4) = va;
        *(float4*)(sA + row * KS1 + 64 + q * 4) = vx;
    }
    __syncthreads();

    int c = tx & 7, r = tx >> 3;
    ull acc[4][8];
    #pragma unroll
    for (int j = 0; j < 8; j++) {
        ull b = ((const ull*)sB)[c + 8 * j];
        acc[0][j] = b; acc[1][j] = b; acc[2][j] = b; acc[3][j] = b;
    }

    const float* a0 = sA + (r * 4 + 0) * KS1;
    const float* a1 = sA + (r * 4 + 1) * KS1;
    const float* a2 = sA + (r * 4 + 2) * KS1;
    const float* a3 = sA + (r * 4 + 3) * KS1;

    #pragma unroll 2
    for (int k = 0; k < HID; k++) {
        ull va0 = pack2(a0[k]);
        ull va1 = pack2(a1[k]);
        ull va2 = pack2(a2[k]);
        ull va3 = pack2(a3[k]);
        const ull* wr = (const ull*)(sW + k * HID);
        #pragma unroll
        for (int j = 0; j < 8; j++) {
            ull w = wr[c + 8 * j];
            fma2(acc[0][j], va0, w);
            fma2(acc[1][j], va1, w);
            fma2(acc[2][j], va2, w);
            fma2(acc[3][j], va3, w);
        }
    }

    // epilogue: per-node L2 norm, relu, store h1, BN col stats
    float cs[16], cq[16];
    #pragma unroll
    for (int t = 0; t < 16; t++) { cs[t] = 0.f; cq[t] = 0.f; }

    #pragma unroll
    for (int i = 0; i < 4; i++) {
        float2 p[8];
        float ss = 0.f;
        #pragma unroll
        for (int j = 0; j < 8; j++) {
            p[j] = unpack2(acc[i][j]);
            ss += p[j].x * p[j].x + p[j].y * p[j].y;
        }
        ss += __shfl_xor_sync(0xffffffffu, ss, 1);
        ss += __shfl_xor_sync(0xffffffffu, ss, 2);
        ss += __shfl_xor_sync(0xffffffffu, ss, 4);
        float inv = 1.0f / fmaxf(sqrtf(ss), 1e-12f);
        int n = nb + r * 4 + i;
        bool ok = (n < N_NODES);
        #pragma unroll
        for (int j = 0; j < 8; j++) {
            float hx = fmaxf(p[j].x * inv, 0.f);
            float hy = fmaxf(p[j].y * inv, 0.f);
            if (!ok) { hx = 0.f; hy = 0.f; }
            else *(float2*)(g_h1 + (size_t)n * HID + (c + 8 * j) * 2) = make_float2(hx, hy);
            cs[2 * j] += hx; cs[2 * j + 1] += hy;
            cq[2 * j] += hx * hx; cq[2 * j + 1] += hy * hy;
        }
    }
    #pragma unroll
    for (int t = 0; t < 16; t++) {
        cs[t] += __shfl_xor_sync(0xffffffffu, cs[t], 8);
        cs[t] += __shfl_xor_sync(0xffffffffu, cs[t], 16);
        cq[t] += __shfl_xor_sync(0xffffffffu, cq[t], 8);
        cq[t] += __shfl_xor_sync(0xffffffffu, cq[t], 16);
    }
    if ((tx & 31) < 8) {
        #pragma unroll
        for (int j = 0; j < 8; j++) {
            atomicAdd(&sSum[(c + 8 * j) * 2],     cs[2 * j]);
            atomicAdd(&sSum[(c + 8 * j) * 2 + 1], cs[2 * j + 1]);
            atomicAdd(&sSq[(c + 8 * j) * 2],      cq[2 * j]);
            atomicAdd(&sSq[(c + 8 * j) * 2 + 1],  cq[2 * j + 1]);
        }
    }
    __syncthreads();
    if (tx < HID) {
        atomicAdd(&g_bnsum[tx], sSum[tx]);
        atomicAdd(&g_bnsq[tx], sSq[tx]);
    }
}

// ---------------- BN finalize ----------------
__global__ void bn_finalize_kernel(const float* __restrict__ gamma,
                                   const float* __restrict__ beta)
{
    int j = threadIdx.x;
    if (j < HID) {
        float mean = g_bnsum[j] / (float)N_NODES;
        float var  = g_bnsq[j] / (float)N_NODES - mean * mean;
        float inv  = rsqrtf(var + 1e-5f);
        float sc   = gamma[j] * inv;
        g_bnscale[j] = sc;
        g_bnshift[j] = beta[j] - mean * sc;
    }
}

// ---------------- gather 2: warp per node, BN fused -------------------------
__global__ __launch_bounds__(256) void gather2_kernel() {
    int warp = threadIdx.x >> 5, lane = threadIdx.x & 31;
    int n = blockIdx.x * 8 + warp;
    if (n >= N_NODES) return;
    int d = g_deg[n], st = g_rowptr[n];
    const float4* h4 = (const float4*)g_h1;
    float4 acc = make_float4(0.f, 0.f, 0.f, 0.f);
    for (int base = 0; base < d; base += 32) {
        int m = min(d - base, 32);
        int ci = (lane < m) ? g_col[st + base + lane] : 0;
        int j = 0;
        for (; j + 4 <= m; j += 4) {
            int s0 = __shfl_sync(0xffffffffu, ci, j);
            int s1 = __shfl_sync(0xffffffffu, ci, j + 1);
            int s2 = __shfl_sync(0xffffffffu, ci, j + 2);
            int s3 = __shfl_sync(0xffffffffu, ci, j + 3);
            float4 v0 = h4[s0 * 32 + lane];
            float4 v1 = h4[s1 * 32 + lane];
            float4 v2 = h4[s2 * 32 + lane];
            float4 v3 = h4[s3 * 32 + lane];
            acc.x += (v0.x + v1.x) + (v2.x + v3.x);
            acc.y += (v0.y + v1.y) + (v2.y + v3.y);
            acc.z += (v0.z + v1.z) + (v2.z + v3.z);
            acc.w += (v0.w + v1.w) + (v2.w + v3.w);
        }
        for (; j < m; j++) {
            int s = __shfl_sync(0xffffffffu, ci, j);
            float4 v = h4[s * 32 + lane];
            acc.x += v.x; acc.y += v.y; acc.z += v.z; acc.w += v.w;
        }
    }
    float rc = 1.0f / fmaxf((float)d, 1.0f);
    float flag = (d > 0) ? 1.0f : 0.0f;
    float4 sc = ((const float4*)g_bnscale)[lane];
    float4 sh = ((const float4*)g_bnshift)[lane];
    float4 ag;
    ag.x = sc.x * acc.x * rc + sh.x * flag;
    ag.y = sc.y * acc.y * rc + sh.y * flag;
    ag.z = sc.z * acc.z * rc + sh.z * flag;
    ag.w = sc.w * acc.w * rc + sh.w * flag;
    ((float4*)g_agg2)[n * 32 + lane] = ag;
}

// ---------------- GEMM 2: [agg2|BN(h1)] @ [w2l;w2r] + b, L2norm, FC ---------
// Both W and A are streamed in K-halves to stay under the 227KB smem limit:
//   pass 0: sW=w2l, sA=agg2 half      pass 1: sW=w2r, sA=BN(h1) half
// smem = (16384 + 128*132 + 512 + 3*128 + 16) * 4 ~= 135 KB
#define SMEMG2 ((HID*HID + MT*KS1 + HID*OUT_DIM/4*0 + 512 + 3*HID + OUT_DIM) * 4)

__global__ __launch_bounds__(256) void gemm2_kernel(
    const float* __restrict__ w2l,
    const float* __restrict__ b2l,
    const float* __restrict__ w2r,
    const float* __restrict__ wfc,
    const float* __restrict__ bfc,
    float* __restrict__ out)
{
    extern __shared__ float sm[];
    float* sW   = sm;                    // [128][128] streamed: w2l then w2r
    float* sA   = sW + HID * HID;        // [128][132] streamed: agg2 then BN(h1)
    float* sWfc = sA + MT * KS1;         // [128][16] -> 512 float4 = 2048 floats
    float* sB   = sWfc + HID * OUT_DIM;
    float* sSc  = sB + HID;
    float* sSh  = sSc + HID;
    float* sBfc = sSh + HID;

    int tx = threadIdx.x;
    if (tx < HID) {
        sB[tx]  = b2l[tx];
        sSc[tx] = g_bnscale[tx];
        sSh[tx] = g_bnshift[tx];
    }
    if (tx < OUT_DIM) sBfc[tx] = bfc[tx];
    for (int i = tx; i < HID * HID / 4; i += 256)
        ((float4*)sW)[i] = ((const float4*)w2l)[i];
    for (int i = tx; i < HID * OUT_DIM / 4; i += 256)
        ((float4*)sWfc)[i] = ((const float4*)wfc)[i];

    int nb = blockIdx.x * MT;
    // stage pass-0 A: agg2 (all 128 K-cols)
    for (int i = tx; i < MT * 32; i += 256) {
        int row = i >> 5, q = i & 31;
        int n = nb + row;
        float4 v = make_float4(0.f, 0.f, 0.f, 0.f);
        if (n < N_NODES) v = ((const float4*)g_agg2)[n * 32 + q];
        *(float4*)(sA + row * KS1 + q * 4) = v;
    }
    __syncthreads();

    int c = tx & 7, r = tx >> 3;
    ull acc[4][8];
    #pragma unroll
    for (int j = 0; j < 8; j++) {
        ull b = ((const ull*)sB)[c + 8 * j];
        acc[0][j] = b; acc[1][j] = b; acc[2][j] = b; acc[3][j] = b;
    }

    #pragma unroll
    for (int pass = 0; pass < 2; pass++) {
        if (pass == 1) {
            __syncthreads();   // pass-0 GEMM reads done
            // re-stage: sW=w2r, sA=BN(h1)
            for (int i = tx; i < HID * HID / 4; i += 256)
                ((float4*)sW)[i] = ((const float4*)w2r)[i];
            for (int i = tx; i < MT * 32; i += 256) {
                int row = i >> 5, q = i & 31;
                int n = nb + row;
                float4 h = make_float4(0.f, 0.f, 0.f, 0.f);
                if (n < N_NODES) h = ((const float4*)g_h1)[n * 32 + q];
                float4 sc = ((const float4*)sSc)[q];
                float4 sh = ((const float4*)sSh)[q];
                float4 v;
                v.x = sc.x * h.x + sh.x;
                v.y = sc.y * h.y + sh.y;
                v.z = sc.z * h.z + sh.z;
                v.w = sc.w * h.w + sh.w;
                *(float4*)(sA + row * KS1 + q * 4) = v;
            }
            __syncthreads();
        }
        const float* a0 = sA + (r * 4 + 0) * KS1;
        const float* a1 = sA + (r * 4 + 1) * KS1;
        const float* a2 = sA + (r * 4 + 2) * KS1;
        const float* a3 = sA + (r * 4 + 3) * KS1;

        #pragma unroll 2
        for (int k = 0; k < HID; k++) {
            ull va0 = pack2(a0[k]);
            ull va1 = pack2(a1[k]);
            ull va2 = pack2(a2[k]);
            ull va3 = pack2(a3[k]);
            const ull* wr = (const ull*)(sW + k * HID);
            #pragma unroll
            for (int j = 0; j < 8; j++) {
                ull w = wr[c + 8 * j];
                fma2(acc[0][j], va0, w);
                fma2(acc[1][j], va1, w);
                fma2(acc[2][j], va2, w);
                fma2(acc[3][j], va3, w);
            }
        }
    }

    // L2 normalize each node row
    float2 p[4][8];
    #pragma unroll
    for (int i = 0; i < 4; i++) {
        float ss = 0.f;
        #pragma unroll
        for (int j = 0; j < 8; j++) {
            p[i][j] = unpack2(acc[i][j]);
            ss += p[i][j].x * p[i][j].x + p[i][j].y * p[i][j].y;
        }
        ss += __shfl_xor_sync(0xffffffffu, ss, 1);
        ss += __shfl_xor_sync(0xffffffffu, ss, 2);
        ss += __shfl_xor_sync(0xffffffffu, ss, 4);
        float inv = 1.0f / fmaxf(sqrtf(ss), 1e-12f);
        #pragma unroll
        for (int j = 0; j < 8; j++) { p[i][j].x *= inv; p[i][j].y *= inv; }
    }
    __syncthreads();   // all reads of sA done; reuse as h2 buffer

    float* sH = sA;    // [128][132]
    #pragma unroll
    for (int i = 0; i < 4; i++)
        #pragma unroll
        for (int j = 0; j < 8; j++)
            *(float2*)(sH + (r * 4 + i) * KS1 + (c + 8 * j) * 2) = p[i][j];
    __syncthreads();

    // FC: 128 nodes x 16 outputs; thread -> (node, half of outputs)
    int node = tx >> 1;
    int half = tx & 1;
    int n = nb + node;
    if (n < N_NODES) {
        float y[8];
        #pragma unroll
        for (int t = 0; t < 8; t++) y[t] = sBfc[half * 8 + t];
        const float* h = sH + node * KS1;
        #pragma unroll 4
        for (int j2 = 0; j2 < HID; j2++) {
            float hv = h[j2];
            float4 w0 = *(const float4*)(sWfc + j2 * OUT_DIM + half * 8);
            float4 w1 = *(const float4*)(sWfc + j2 * OUT_DIM + half * 8 + 4);
            y[0] += hv * w0.x; y[1] += hv * w0.y; y[2] += hv * w0.z; y[3] += hv * w0.w;
            y[4] += hv * w1.x; y[5] += hv * w1.y; y[6] += hv * w1.z; y[7] += hv * w1.w;
        }
        *(float4*)(out + (size_t)n * OUT_DIM + half * 8)     = make_float4(y[0], y[1], y[2], y[3]);
        *(float4*)(out + (size_t)n * OUT_DIM + half * 8 + 4) = make_float4(y[4], y[5], y[6], y[7]);
    }
}

// actual smem for gemm2 (recompute cleanly)
#define SMEMG2_REAL ((HID*HID + MT*KS1 + HID*OUT_DIM + 3*HID + OUT_DIM) * 4)

// ---------------- launch ----------------------------------------------------
extern "C" void kernel_launch(void* const* d_in, const int* in_sizes, int n_in,
                              void* d_out, int out_size)
{
    const float* x     = (const float*)d_in[0];
    const int*   ei    = (const int*)d_in[1];
    const float* w1l   = (const float*)d_in[2];
    const float* b1l   = (const float*)d_in[3];
    const float* w1r   = (const float*)d_in[4];
    const float* gamma = (const float*)d_in[5];
    const float* beta  = (const float*)d_in[6];
    const float* w2l   = (const float*)d_in[7];
    const float* b2l   = (const float*)d_in[8];
    const float* w2r   = (const float*)d_in[9];
    const float* wfc   = (const float*)d_in[10];
    const float* bfc   = (const float*)d_in[11];
    float* out = (float*)d_out;

    cudaFuncSetAttribute(gemm1_kernel, cudaFuncAttributeMaxDynamicSharedMemorySize, SMEMG1);
    cudaFuncSetAttribute(gemm2_kernel, cudaFuncAttributeMaxDynamicSharedMemorySize, SMEMG2_REAL);

    int ng = (N_NODES + 255) / 256;        // 391
    int eg = (N_EDGES + 255) / 256;        // 6250
    int gg = (N_NODES + 7) / 8;            // 12500 (gather: 8 nodes/block)
    int mg = (N_NODES + MT - 1) / MT;      // 782

    zero_kernel<<<ng, 256>>>();
    hist_kernel<<<eg, 256>>>(ei);
    scan_chunk_kernel<<<NCHUNK, CHUNK>>>();
    scan_tops_kernel<<<1, 256>>>();
    add_off_kernel<<<ng, 256>>>();
    fill_kernel<<<eg, 256>>>(ei);
    gather1_kernel<<<gg, 256>>>(x);
    gemm1_kernel<<<mg, 256, SMEMG1>>>(x, w1l, w1r, b1l);
    bn_finalize_kernel<<<1, 128>>>(gamma, beta);
    gather2_kernel<<<gg, 256>>>();
    gemm2_kernel<<<mg, 256, SMEMG2_REAL>>>(w2l, b2l, w2r, wfc, bfc, out);
}